// round 3
// baseline (speedup 1.0000x reference)
#include <cuda_runtime.h>
#include <cuda_bf16.h>

#define N_NODES 50000
#define N_EDGES 800000
#define FEAT 10
#define HID 64
#define N_SHEETS 256
#define SHEET_LEN 128

// ---------------- scratch (static device globals; no allocation) ----------------
__device__ float d_hA[N_NODES * HID];      // gemm output / agg input
__device__ float d_hB[N_NODES * HID];      // agg output / next gemm input
__device__ int   d_deg[N_NODES];
__device__ float d_dinv[N_NODES];
__device__ int   d_rowptr[N_NODES + 1];
__device__ int   d_rowcur[N_NODES];
__device__ int   d_csrsrc[N_EDGES];
__device__ float d_sheet[N_SHEETS * HID];
__device__ float d_gsum[HID];

// ---------------- kernels ----------------

__global__ void zero_kernel(int* deg, float* gsum, int n) {
    int i = blockIdx.x * blockDim.x + threadIdx.x;
    if (i < n) deg[i] = 0;
    if (i < HID) gsum[i] = 0.f;
}

__global__ void deg_kernel(const int* __restrict__ dst, int* __restrict__ deg, int nE) {
    int e = blockIdx.x * blockDim.x + threadIdx.x;
    if (e < nE) atomicAdd(&deg[dst[e]], 1);
}

__global__ void dinv_kernel(const int* __restrict__ deg, float* __restrict__ dinv, int n) {
    int i = blockIdx.x * blockDim.x + threadIdx.x;
    if (i < n) dinv[i] = rsqrtf((float)deg[i] + 1.0f);
}

// single-block exclusive scan over deg -> row_ptr (and row_cur copy)
__global__ void scan_kernel(const int* __restrict__ deg, int* __restrict__ row_ptr,
                            int* __restrict__ row_cur, int n) {
    __shared__ int warp_sums[32];
    __shared__ int s_carry;
    int tid = threadIdx.x;
    int lane = tid & 31, wrp = tid >> 5;
    if (tid == 0) s_carry = 0;
    __syncthreads();
    for (int base = 0; base < n; base += 1024) {
        int i = base + tid;
        int v = (i < n) ? deg[i] : 0;
        int x = v;
        #pragma unroll
        for (int off = 1; off < 32; off <<= 1) {
            int y = __shfl_up_sync(0xffffffffu, x, off);
            if (lane >= off) x += y;
        }
        if (lane == 31) warp_sums[wrp] = x;
        __syncthreads();
        if (wrp == 0) {
            int y = warp_sums[lane];
            #pragma unroll
            for (int off = 1; off < 32; off <<= 1) {
                int z = __shfl_up_sync(0xffffffffu, y, off);
                if (lane >= off) y += z;
            }
            warp_sums[lane] = y;
        }
        __syncthreads();
        int incl = x + (wrp > 0 ? warp_sums[wrp - 1] : 0);
        int excl = incl - v + s_carry;
        if (i < n) { row_ptr[i] = excl; row_cur[i] = excl; }
        __syncthreads();
        if (tid == 1023) s_carry += incl;
        __syncthreads();
    }
    if (tid == 0) row_ptr[n] = s_carry;
}

__global__ void scatter_kernel(const int* __restrict__ src, const int* __restrict__ dst,
                               int* __restrict__ rowcur, int* __restrict__ csrsrc, int nE) {
    int e = blockIdx.x * blockDim.x + threadIdx.x;
    if (e >= nE) return;
    int d = dst[e];
    int p = atomicAdd(&rowcur[d], 1);
    csrsrc[p] = src[e];
}

// H = X @ W  (X: [n,K], W: [K,64]).  One thread per node, W staged in smem.
template <int K>
__global__ void gemm_kernel(const float* __restrict__ X, const float* __restrict__ W,
                            float* __restrict__ H, int n) {
    __shared__ __align__(16) float Wsm[K * HID];
    int tid = threadIdx.x;
    for (int i = tid; i < K * HID; i += blockDim.x) Wsm[i] = W[i];
    __syncthreads();
    int node = blockIdx.x * blockDim.x + tid;
    if (node >= n) return;
    float acc[HID];
    #pragma unroll
    for (int j = 0; j < HID; j++) acc[j] = 0.f;
    const float* xr = X + (size_t)node * K;
    #pragma unroll 2
    for (int k = 0; k < K; k++) {
        float xv = __ldg(&xr[k]);
        const float4* wr = (const float4*)&Wsm[k * HID];
        #pragma unroll
        for (int j = 0; j < 16; j++) {
            float4 w = wr[j];
            acc[4*j+0] = fmaf(xv, w.x, acc[4*j+0]);
            acc[4*j+1] = fmaf(xv, w.y, acc[4*j+1]);
            acc[4*j+2] = fmaf(xv, w.z, acc[4*j+2]);
            acc[4*j+3] = fmaf(xv, w.w, acc[4*j+3]);
        }
    }
    float4* orow = (float4*)(H + (size_t)node * HID);
    #pragma unroll
    for (int j = 0; j < 16; j++)
        orow[j] = make_float4(acc[4*j], acc[4*j+1], acc[4*j+2], acc[4*j+3]);
}

// out = relu(dinv_i * (sum_e dinv_src * h_src + h_i * dinv_i) + b).  Warp per node.
__global__ void agg_kernel(const float* __restrict__ H, const int* __restrict__ row_ptr,
                           const int* __restrict__ csrsrc, const float* __restrict__ dinv,
                           const float* __restrict__ b, float* __restrict__ out, int n) {
    int warp = (blockIdx.x * blockDim.x + threadIdx.x) >> 5;
    int lane = threadIdx.x & 31;
    if (warp >= n) return;
    int beg = row_ptr[warp];
    int end = row_ptr[warp + 1];
    float acc0 = 0.f, acc1 = 0.f;
    for (int e = beg; e < end; e++) {
        int s = csrsrc[e];                 // warp-uniform
        float w = dinv[s];                 // warp-uniform
        acc0 = fmaf(w, H[(size_t)s * HID + lane], acc0);
        acc1 = fmaf(w, H[(size_t)s * HID + 32 + lane], acc1);
    }
    float di = dinv[warp];
    float h0 = H[(size_t)warp * HID + lane];
    float h1 = H[(size_t)warp * HID + 32 + lane];
    acc0 = di * fmaf(h0, di, acc0) + b[lane];
    acc1 = di * fmaf(h1, di, acc1) + b[lane + 32];
    out[(size_t)warp * HID + lane]      = fmaxf(acc0, 0.f);
    out[(size_t)warp * HID + 32 + lane] = fmaxf(acc1, 0.f);
}

// one block (64 threads) per sheet: mean over 128 gathered rows
__global__ void sheet_kernel(const float* __restrict__ H, const int* __restrict__ idx,
                             float* __restrict__ sheet_embs) {
    int s = blockIdx.x;
    int f = threadIdx.x;
    const int* row = idx + s * SHEET_LEN;
    float acc = 0.f;
    #pragma unroll 4
    for (int n = 0; n < SHEET_LEN; n++) {
        int node = row[n];                 // warp-uniform
        acc += H[(size_t)node * HID + f];
    }
    sheet_embs[s * HID + f] = acc * (1.0f / SHEET_LEN);
}

// grid-stride partial sums -> atomicAdd into gsum[64]
__global__ void gsum_kernel(const float* __restrict__ H, float* __restrict__ gsum, int n) {
    int f = threadIdx.x;
    float acc = 0.f;
    for (int i = blockIdx.x; i < n; i += gridDim.x)
        acc += H[(size_t)i * HID + f];
    atomicAdd(&gsum[f], acc);
}

// per-sheet tail MLPs: geo MLP, fusion, q head.  Block (64 threads) per sheet.
__global__ void tail_kernel(const float* __restrict__ sheet_embs,
                            const float* __restrict__ sheet_feat,
                            const float* __restrict__ geoW1, const float* __restrict__ geob1,
                            const float* __restrict__ geoW2, const float* __restrict__ geob2,
                            const float* __restrict__ fusW,  const float* __restrict__ fusb,
                            const float* __restrict__ qW1,   const float* __restrict__ qb1,
                            const float* __restrict__ qW2,   const float* __restrict__ qb2,
                            const float* __restrict__ gsum, float inv_n,
                            float* __restrict__ out) {
    __shared__ float sf[FEAT], t1[HID], geo[HID], se[HID], fused[HID], g[HID];
    __shared__ float red[2];
    int s = blockIdx.x, j = threadIdx.x;
    if (j < FEAT) sf[j] = sheet_feat[s * FEAT + j];
    se[j] = sheet_embs[s * HID + j];
    g[j]  = gsum[j] * inv_n;
    __syncthreads();

    float a = geob1[j];
    #pragma unroll
    for (int k = 0; k < FEAT; k++) a = fmaf(sf[k], geoW1[k * HID + j], a);
    t1[j] = fmaxf(a, 0.f);
    __syncthreads();

    a = geob2[j];
    #pragma unroll 8
    for (int k = 0; k < HID; k++) a = fmaf(t1[k], geoW2[k * HID + j], a);
    geo[j] = a;
    __syncthreads();

    a = fusb[j];
    #pragma unroll 8
    for (int k = 0; k < HID; k++) a = fmaf(se[k],  fusW[k * HID + j], a);
    #pragma unroll 8
    for (int k = 0; k < HID; k++) a = fmaf(geo[k], fusW[(HID + k) * HID + j], a);
    fused[j] = fmaxf(a, 0.f);
    __syncthreads();

    a = qb1[j];
    #pragma unroll 8
    for (int k = 0; k < HID; k++) a = fmaf(fused[k], qW1[k * HID + j], a);
    #pragma unroll 8
    for (int k = 0; k < HID; k++) a = fmaf(g[k],     qW1[(HID + k) * HID + j], a);
    float q = fmaxf(a, 0.f) * qW2[j];

    // reduce over 64 threads (2 warps)
    #pragma unroll
    for (int off = 16; off; off >>= 1) q += __shfl_down_sync(0xffffffffu, q, off);
    if ((j & 31) == 0) red[j >> 5] = q;
    __syncthreads();
    if (j == 0) out[s] = red[0] + red[1] + qb2[0];
}

// ---------------- launch ----------------

extern "C" void kernel_launch(void* const* d_in, const int* in_sizes, int n_in,
                              void* d_out, int out_size) {
    const float* x          = (const float*)d_in[0];
    const int*   ei         = (const int*)d_in[1];   // [2, E], int32
    const int*   sheet_idx  = (const int*)d_in[3];
    const float* sheet_feat = (const float*)d_in[4];
    const float* W1 = (const float*)d_in[5];  const float* b1 = (const float*)d_in[6];
    const float* W2 = (const float*)d_in[7];  const float* b2 = (const float*)d_in[8];
    const float* W3 = (const float*)d_in[9];  const float* b3 = (const float*)d_in[10];
    const float* gW1 = (const float*)d_in[11]; const float* gb1 = (const float*)d_in[12];
    const float* gW2 = (const float*)d_in[13]; const float* gb2 = (const float*)d_in[14];
    const float* fW  = (const float*)d_in[15]; const float* fb  = (const float*)d_in[16];
    const float* qW1 = (const float*)d_in[17]; const float* qb1 = (const float*)d_in[18];
    const float* qW2 = (const float*)d_in[19]; const float* qb2 = (const float*)d_in[20];
    float* out = (float*)d_out;

    const int* src = ei;
    const int* dst = ei + N_EDGES;

    float *hA, *hB, *dinv, *sheet, *gsum;
    int *deg, *rowptr, *rowcur, *csrsrc;
    cudaGetSymbolAddress((void**)&hA, d_hA);
    cudaGetSymbolAddress((void**)&hB, d_hB);
    cudaGetSymbolAddress((void**)&deg, d_deg);
    cudaGetSymbolAddress((void**)&dinv, d_dinv);
    cudaGetSymbolAddress((void**)&rowptr, d_rowptr);
    cudaGetSymbolAddress((void**)&rowcur, d_rowcur);
    cudaGetSymbolAddress((void**)&csrsrc, d_csrsrc);
    cudaGetSymbolAddress((void**)&sheet, d_sheet);
    cudaGetSymbolAddress((void**)&gsum, d_gsum);

    // graph structure (rebuilt every call; input-dependent only -> deterministic work)
    zero_kernel<<<(N_NODES + 255) / 256, 256>>>(deg, gsum, N_NODES);
    deg_kernel<<<(N_EDGES + 255) / 256, 256>>>(dst, deg, N_EDGES);
    dinv_kernel<<<(N_NODES + 255) / 256, 256>>>(deg, dinv, N_NODES);
    scan_kernel<<<1, 1024>>>(deg, rowptr, rowcur, N_NODES);
    scatter_kernel<<<(N_EDGES + 255) / 256, 256>>>(src, dst, rowcur, csrsrc, N_EDGES);

    const int gemm_grid = (N_NODES + 127) / 128;
    const int agg_grid  = (N_NODES * 32 + 255) / 256;

    // layer 1
    gemm_kernel<FEAT><<<gemm_grid, 128>>>(x, W1, hA, N_NODES);
    agg_kernel<<<agg_grid, 256>>>(hA, rowptr, csrsrc, dinv, b1, hB, N_NODES);
    // layer 2
    gemm_kernel<HID><<<gemm_grid, 128>>>(hB, W2, hA, N_NODES);
    agg_kernel<<<agg_grid, 256>>>(hA, rowptr, csrsrc, dinv, b2, hB, N_NODES);
    // layer 3
    gemm_kernel<HID><<<gemm_grid, 128>>>(hB, W3, hA, N_NODES);
    agg_kernel<<<agg_grid, 256>>>(hA, rowptr, csrsrc, dinv, b3, hB, N_NODES);

    // pooling
    sheet_kernel<<<N_SHEETS, HID>>>(hB, sheet_idx, sheet);
    gsum_kernel<<<256, HID>>>(hB, gsum, N_NODES);

    // tail MLPs
    tail_kernel<<<N_SHEETS, HID>>>(sheet, sheet_feat,
                                   gW1, gb1, gW2, gb2, fW, fb, qW1, qb1, qW2, qb2,
                                   gsum, 1.0f / N_NODES, out);
}

// round 7
// speedup vs baseline: 1.0887x; 1.0887x over previous
#include <cuda_runtime.h>
#include <cuda_bf16.h>

#define N_NODES 50000
#define N_EDGES 800000
#define FEAT 10
#define HID 64
#define N_SHEETS 256
#define SHEET_LEN 128

#define SCAN_BLK 512
#define SCAN_GRID ((N_NODES + SCAN_BLK - 1) / SCAN_BLK)   // 98

// ---------------- scratch (static device globals; no allocation) ----------------
__device__ float d_hA[N_NODES * HID];      // gemm output / agg input
__device__ float d_hB[N_NODES * HID];      // agg output / next gemm input
__device__ int   d_deg[N_NODES];
__device__ float d_dinv[N_NODES];
__device__ int   d_rowptr[N_NODES + 1];
__device__ int   d_rowcur[N_NODES];
__device__ int   d_csrsrc[N_EDGES];
__device__ int   d_part[SCAN_GRID + 32];
__device__ float d_sheet[N_SHEETS * HID];
__device__ float d_gsum[HID];

// ---------------- kernels ----------------

__global__ void zero_kernel(int* deg, float* gsum, int n) {
    int i = blockIdx.x * blockDim.x + threadIdx.x;
    if (i < n) deg[i] = 0;
    if (i < HID) gsum[i] = 0.f;
}

__global__ void deg_kernel(const int* __restrict__ dst, int* __restrict__ deg, int nE) {
    int e = blockIdx.x * blockDim.x + threadIdx.x;
    if (e < nE) atomicAdd(&deg[dst[e]], 1);
}

// pass 1: per-block sums of deg, plus dinv (reads deg anyway)
__global__ void scan1_kernel(const int* __restrict__ deg, float* __restrict__ dinv,
                             int* __restrict__ partials, int n) {
    __shared__ int ws[SCAN_BLK / 32];
    int i = blockIdx.x * blockDim.x + threadIdx.x;
    int lane = threadIdx.x & 31, wrp = threadIdx.x >> 5;
    int v = (i < n) ? deg[i] : 0;
    if (i < n) dinv[i] = rsqrtf((float)v + 1.0f);
    int s = v;
    #pragma unroll
    for (int off = 16; off; off >>= 1) s += __shfl_down_sync(0xffffffffu, s, off);
    if (lane == 0) ws[wrp] = s;
    __syncthreads();
    if (wrp == 0) {
        int t = (lane < SCAN_BLK / 32) ? ws[lane] : 0;
        #pragma unroll
        for (int off = 16; off; off >>= 1) t += __shfl_down_sync(0xffffffffu, t, off);
        if (lane == 0) partials[blockIdx.x] = t;
    }
}

// pass 2: exclusive scan of the 98 block partials (single block, 128 threads)
__global__ void scan2_kernel(int* __restrict__ partials, int nb, int* __restrict__ total_dst) {
    __shared__ int ws[4];
    int t = threadIdx.x;
    int lane = t & 31, wrp = t >> 5;
    int v = (t < nb) ? partials[t] : 0;
    int x = v;
    #pragma unroll
    for (int off = 1; off < 32; off <<= 1) {
        int y = __shfl_up_sync(0xffffffffu, x, off);
        if (lane >= off) x += y;
    }
    if (lane == 31) ws[wrp] = x;
    __syncthreads();
    if (wrp == 0 && lane < 4) {
        int y = ws[lane];
        #pragma unroll
        for (int off = 1; off < 4; off <<= 1) {
            int z = __shfl_up_sync(0x0000000fu, y, off);
            if (lane >= off) y += z;
        }
        ws[lane] = y;
    }
    __syncthreads();
    int incl = x + (wrp > 0 ? ws[wrp - 1] : 0);
    if (t < nb) partials[t] = incl - v;          // exclusive
    if (t == 127) *total_dst = incl;             // total (rowptr[N])
}

// pass 3: per-block rescan + offset -> rowptr/rowcur
__global__ void scan3_kernel(const int* __restrict__ deg, const int* __restrict__ partials,
                             int* __restrict__ row_ptr, int* __restrict__ row_cur, int n) {
    __shared__ int ws[SCAN_BLK / 32];
    int i = blockIdx.x * blockDim.x + threadIdx.x;
    int lane = threadIdx.x & 31, wrp = threadIdx.x >> 5;
    int v = (i < n) ? deg[i] : 0;
    int x = v;
    #pragma unroll
    for (int off = 1; off < 32; off <<= 1) {
        int y = __shfl_up_sync(0xffffffffu, x, off);
        if (lane >= off) x += y;
    }
    if (lane == 31) ws[wrp] = x;
    __syncthreads();
    if (wrp == 0) {
        int y = (lane < SCAN_BLK / 32) ? ws[lane] : 0;
        #pragma unroll
        for (int off = 1; off < 16; off <<= 1) {
            int z = __shfl_up_sync(0xffffffffu, y, off);
            if (lane >= off) y += z;
        }
        if (lane < SCAN_BLK / 32) ws[lane] = y;
    }
    __syncthreads();
    int excl = x - v + (wrp > 0 ? ws[wrp - 1] : 0) + partials[blockIdx.x];
    if (i < n) { row_ptr[i] = excl; row_cur[i] = excl; }
}

__global__ void scatter_kernel(const int* __restrict__ src, const int* __restrict__ dst,
                               int* __restrict__ rowcur, int* __restrict__ csrsrc, int nE) {
    int e = blockIdx.x * blockDim.x + threadIdx.x;
    if (e >= nE) return;
    int d = dst[e];
    int p = atomicAdd(&rowcur[d], 1);
    csrsrc[p] = src[e];
}

// layer-1 trick: aggregate the RAW features (A·X), 10-wide, before the GEMM.
// out[i,f] = dinv_i * (sum_e dinv_src * x[src,f] + x[i,f]*dinv_i)   (no bias/relu)
__global__ void aggx_kernel(const float* __restrict__ X, const int* __restrict__ row_ptr,
                            const int* __restrict__ csrsrc, const float* __restrict__ dinv,
                            float* __restrict__ out, int n) {
    int warp = (blockIdx.x * blockDim.x + threadIdx.x) >> 5;
    int lane = threadIdx.x & 31;
    if (warp >= n) return;
    int beg = row_ptr[warp];
    int end = row_ptr[warp + 1];
    float acc = 0.f;
    for (int e = beg; e < end; e++) {
        int s = csrsrc[e];                 // warp-uniform
        float w = dinv[s];                 // warp-uniform
        if (lane < FEAT)
            acc = fmaf(w, X[(size_t)s * FEAT + lane], acc);
    }
    if (lane < FEAT) {
        float di = dinv[warp];
        float xv = X[(size_t)warp * FEAT + lane];
        out[(size_t)warp * FEAT + lane] = di * fmaf(xv, di, acc);
    }
}

// H = X @ W (+b, relu if BIASRELU).  One thread per node, W staged in smem.
template <int K, bool BIASRELU>
__global__ void gemm_kernel(const float* __restrict__ X, const float* __restrict__ W,
                            const float* __restrict__ b, float* __restrict__ H, int n) {
    __shared__ __align__(16) float Wsm[K * HID];
    __shared__ float bsm[HID];
    int tid = threadIdx.x;
    for (int i = tid; i < K * HID; i += blockDim.x) Wsm[i] = W[i];
    if (BIASRELU && tid < HID) bsm[tid] = b[tid];
    __syncthreads();
    int node = blockIdx.x * blockDim.x + tid;
    if (node >= n) return;
    float acc[HID];
    #pragma unroll
    for (int j = 0; j < HID; j++) acc[j] = 0.f;
    const float* xr = X + (size_t)node * K;
    #pragma unroll 2
    for (int k = 0; k < K; k++) {
        float xv = __ldg(&xr[k]);
        const float4* wr = (const float4*)&Wsm[k * HID];
        #pragma unroll
        for (int j = 0; j < 16; j++) {
            float4 w = wr[j];
            acc[4*j+0] = fmaf(xv, w.x, acc[4*j+0]);
            acc[4*j+1] = fmaf(xv, w.y, acc[4*j+1]);
            acc[4*j+2] = fmaf(xv, w.z, acc[4*j+2]);
            acc[4*j+3] = fmaf(xv, w.w, acc[4*j+3]);
        }
    }
    float4* orow = (float4*)(H + (size_t)node * HID);
    #pragma unroll
    for (int j = 0; j < 16; j++) {
        float4 v = make_float4(acc[4*j], acc[4*j+1], acc[4*j+2], acc[4*j+3]);
        if (BIASRELU) {
            v.x = fmaxf(v.x + bsm[4*j+0], 0.f);
            v.y = fmaxf(v.y + bsm[4*j+1], 0.f);
            v.z = fmaxf(v.z + bsm[4*j+2], 0.f);
            v.w = fmaxf(v.w + bsm[4*j+3], 0.f);
        }
        orow[j] = v;
    }
}

// out = relu(dinv_i * (sum_e dinv_src * h_src + h_i * dinv_i) + b).  Warp per node.
__global__ void agg_kernel(const float* __restrict__ H, const int* __restrict__ row_ptr,
                           const int* __restrict__ csrsrc, const float* __restrict__ dinv,
                           const float* __restrict__ b, float* __restrict__ out, int n) {
    int warp = (blockIdx.x * blockDim.x + threadIdx.x) >> 5;
    int lane = threadIdx.x & 31;
    if (warp >= n) return;
    int beg = row_ptr[warp];
    int end = row_ptr[warp + 1];
    float acc0 = 0.f, acc1 = 0.f;
    for (int e = beg; e < end; e++) {
        int s = csrsrc[e];                 // warp-uniform
        float w = dinv[s];                 // warp-uniform
        acc0 = fmaf(w, H[(size_t)s * HID + lane], acc0);
        acc1 = fmaf(w, H[(size_t)s * HID + 32 + lane], acc1);
    }
    float di = dinv[warp];
    float h0 = H[(size_t)warp * HID + lane];
    float h1 = H[(size_t)warp * HID + 32 + lane];
    acc0 = di * fmaf(h0, di, acc0) + b[lane];
    acc1 = di * fmaf(h1, di, acc1) + b[lane + 32];
    out[(size_t)warp * HID + lane]      = fmaxf(acc0, 0.f);
    out[(size_t)warp * HID + 32 + lane] = fmaxf(acc1, 0.f);
}

// one block (64 threads) per sheet: mean over 128 gathered rows
__global__ void sheet_kernel(const float* __restrict__ H, const int* __restrict__ idx,
                             float* __restrict__ sheet_embs) {
    int s = blockIdx.x;
    int f = threadIdx.x;
    const int* row = idx + s * SHEET_LEN;
    float acc = 0.f;
    #pragma unroll 4
    for (int n = 0; n < SHEET_LEN; n++) {
        int node = row[n];                 // warp-uniform
        acc += H[(size_t)node * HID + f];
    }
    sheet_embs[s * HID + f] = acc * (1.0f / SHEET_LEN);
}

// grid-stride partial sums -> atomicAdd into gsum[64]
__global__ void gsum_kernel(const float* __restrict__ H, float* __restrict__ gsum, int n) {
    int f = threadIdx.x;
    float acc = 0.f;
    for (int i = blockIdx.x; i < n; i += gridDim.x)
        acc += H[(size_t)i * HID + f];
    atomicAdd(&gsum[f], acc);
}

// per-sheet tail MLPs: geo MLP, fusion, q head.  Block (64 threads) per sheet.
__global__ void tail_kernel(const float* __restrict__ sheet_embs,
                            const float* __restrict__ sheet_feat,
                            const float* __restrict__ geoW1, const float* __restrict__ geob1,
                            const float* __restrict__ geoW2, const float* __restrict__ geob2,
                            const float* __restrict__ fusW,  const float* __restrict__ fusb,
                            const float* __restrict__ qW1,   const float* __restrict__ qb1,
                            const float* __restrict__ qW2,   const float* __restrict__ qb2,
                            const float* __restrict__ gsum, float inv_n,
                            float* __restrict__ out) {
    __shared__ float sf[FEAT], t1[HID], geo[HID], se[HID], fused[HID], g[HID];
    __shared__ float red[2];
    int s = blockIdx.x, j = threadIdx.x;
    if (j < FEAT) sf[j] = sheet_feat[s * FEAT + j];
    se[j] = sheet_embs[s * HID + j];
    g[j]  = gsum[j] * inv_n;
    __syncthreads();

    float a = geob1[j];
    #pragma unroll
    for (int k = 0; k < FEAT; k++) a = fmaf(sf[k], geoW1[k * HID + j], a);
    t1[j] = fmaxf(a, 0.f);
    __syncthreads();

    a = geob2[j];
    #pragma unroll 8
    for (int k = 0; k < HID; k++) a = fmaf(t1[k], geoW2[k * HID + j], a);
    geo[j] = a;
    __syncthreads();

    a = fusb[j];
    #pragma unroll 8
    for (int k = 0; k < HID; k++) a = fmaf(se[k],  fusW[k * HID + j], a);
    #pragma unroll 8
    for (int k = 0; k < HID; k++) a = fmaf(geo[k], fusW[(HID + k) * HID + j], a);
    fused[j] = fmaxf(a, 0.f);
    __syncthreads();

    a = qb1[j];
    #pragma unroll 8
    for (int k = 0; k < HID; k++) a = fmaf(fused[k], qW1[k * HID + j], a);
    #pragma unroll 8
    for (int k = 0; k < HID; k++) a = fmaf(g[k],     qW1[(HID + k) * HID + j], a);
    float q = fmaxf(a, 0.f) * qW2[j];

    #pragma unroll
    for (int off = 16; off; off >>= 1) q += __shfl_down_sync(0xffffffffu, q, off);
    if ((j & 31) == 0) red[j >> 5] = q;
    __syncthreads();
    if (j == 0) out[s] = red[0] + red[1] + qb2[0];
}

// ---------------- launch ----------------

extern "C" void kernel_launch(void* const* d_in, const int* in_sizes, int n_in,
                              void* d_out, int out_size) {
    const float* x          = (const float*)d_in[0];
    const int*   ei         = (const int*)d_in[1];   // [2, E], int32
    const int*   sheet_idx  = (const int*)d_in[3];
    const float* sheet_feat = (const float*)d_in[4];
    const float* W1 = (const float*)d_in[5];  const float* b1 = (const float*)d_in[6];
    const float* W2 = (const float*)d_in[7];  const float* b2 = (const float*)d_in[8];
    const float* W3 = (const float*)d_in[9];  const float* b3 = (const float*)d_in[10];
    const float* gW1 = (const float*)d_in[11]; const float* gb1 = (const float*)d_in[12];
    const float* gW2 = (const float*)d_in[13]; const float* gb2 = (const float*)d_in[14];
    const float* fW  = (const float*)d_in[15]; const float* fb  = (const float*)d_in[16];
    const float* qW1 = (const float*)d_in[17]; const float* qb1 = (const float*)d_in[18];
    const float* qW2 = (const float*)d_in[19]; const float* qb2 = (const float*)d_in[20];
    float* out = (float*)d_out;

    const int* src = ei;
    const int* dst = ei + N_EDGES;

    float *hA, *hB, *dinv, *sheet, *gsum;
    int *deg, *rowptr, *rowcur, *csrsrc, *part;
    cudaGetSymbolAddress((void**)&hA, d_hA);
    cudaGetSymbolAddress((void**)&hB, d_hB);
    cudaGetSymbolAddress((void**)&deg, d_deg);
    cudaGetSymbolAddress((void**)&dinv, d_dinv);
    cudaGetSymbolAddress((void**)&rowptr, d_rowptr);
    cudaGetSymbolAddress((void**)&rowcur, d_rowcur);
    cudaGetSymbolAddress((void**)&csrsrc, d_csrsrc);
    cudaGetSymbolAddress((void**)&part, d_part);
    cudaGetSymbolAddress((void**)&sheet, d_sheet);
    cudaGetSymbolAddress((void**)&gsum, d_gsum);

    // --- CSR build (decoupled 3-pass scan, dinv folded into pass 1) ---
    zero_kernel<<<(N_NODES + 255) / 256, 256>>>(deg, gsum, N_NODES);
    deg_kernel<<<(N_EDGES + 255) / 256, 256>>>(dst, deg, N_EDGES);
    scan1_kernel<<<SCAN_GRID, SCAN_BLK>>>(deg, dinv, part, N_NODES);
    scan2_kernel<<<1, 128>>>(part, SCAN_GRID, rowptr + N_NODES);
    scan3_kernel<<<SCAN_GRID, SCAN_BLK>>>(deg, part, rowptr, rowcur, N_NODES);
    scatter_kernel<<<(N_EDGES + 255) / 256, 256>>>(src, dst, rowcur, csrsrc, N_EDGES);

    const int gemm_grid = (N_NODES + 127) / 128;
    const int agg_grid  = (N_NODES * 32 + 255) / 256;

    // layer 1: (A·X)·W1  — aggregate the 10-wide raw features first
    aggx_kernel<<<agg_grid, 256>>>(x, rowptr, csrsrc, dinv, hA, N_NODES);
    gemm_kernel<FEAT, true><<<gemm_grid, 128>>>(hA, W1, b1, hB, N_NODES);
    // layer 2
    gemm_kernel<HID, false><<<gemm_grid, 128>>>(hB, W2, nullptr, hA, N_NODES);
    agg_kernel<<<agg_grid, 256>>>(hA, rowptr, csrsrc, dinv, b2, hB, N_NODES);
    // layer 3
    gemm_kernel<HID, false><<<gemm_grid, 128>>>(hB, W3, nullptr, hA, N_NODES);
    agg_kernel<<<agg_grid, 256>>>(hA, rowptr, csrsrc, dinv, b3, hB, N_NODES);

    // pooling
    sheet_kernel<<<N_SHEETS, HID>>>(hB, sheet_idx, sheet);
    gsum_kernel<<<256, HID>>>(hB, gsum, N_NODES);

    // tail MLPs
    tail_kernel<<<N_SHEETS, HID>>>(sheet, sheet_feat,
                                   gW1, gb1, gW2, gb2, fW, fb, qW1, qb1, qW2, qb2,
                                   gsum, 1.0f / N_NODES, out);
}